// round 6
// baseline (speedup 1.0000x reference)
#include <cuda_runtime.h>

// ---------------------------------------------------------------------------
// Problem constants
// ---------------------------------------------------------------------------
#define BZ   16
#define SQ   2048
#define HD   768
#define EZ   128
#define NTAG 10
#define H3   2304
#define M_ALL (BZ * SQ)            // 32768
#define START_SIZE (M_ALL * NTAG)  // 327680
#define INV96 (1.0f / 96.0f)
#define KTILES 24                  // 768 / 32
#define NT 512                     // threads per CTA (16 warps, 4x4 grid)

// Scratch
__device__ float g_k[M_ALL * HD];
__device__ float g_q[BZ * EZ * HD];

// ---------------------------------------------------------------------------
// PTX helpers
// ---------------------------------------------------------------------------
__device__ __forceinline__ unsigned s2u(const void* p) {
    unsigned a;
    asm("{ .reg .u64 t; cvta.to.shared.u64 t, %1; cvt.u32.u64 %0, t; }"
        : "=r"(a) : "l"(p));
    return a;
}
__device__ __forceinline__ unsigned rna(float x) {
    unsigned r;
    asm("cvt.rna.tf32.f32 %0, %1;" : "=r"(r) : "f"(x));
    return r;
}
__device__ __forceinline__ float lds32(unsigned a) {
    float v;
    asm volatile("ld.shared.f32 %0, [%1];" : "=f"(v) : "r"(a));
    return v;
}
__device__ __forceinline__ void cpa16(unsigned d, const float* s) {
    asm volatile("cp.async.cg.shared.global [%0], [%1], 16;" :: "r"(d), "l"(s));
}
__device__ __forceinline__ void cpa_commit() {
    asm volatile("cp.async.commit_group;" ::: "memory");
}
__device__ __forceinline__ void cpa_wait1() {
    asm volatile("cp.async.wait_group 1;" ::: "memory");
}
__device__ __forceinline__ void mma8(float d[4], unsigned a0, unsigned a1,
                                     unsigned a2, unsigned a3,
                                     unsigned b0, unsigned b1) {
    asm volatile(
        "mma.sync.aligned.m16n8k8.row.col.f32.tf32.tf32.f32 "
        "{%0,%1,%2,%3}, {%4,%5,%6,%7}, {%8,%9}, {%0,%1,%2,%3};"
        : "+f"(d[0]), "+f"(d[1]), "+f"(d[2]), "+f"(d[3])
        : "r"(a0), "r"(a1), "r"(a2), "r"(a3), "r"(b0), "r"(b1));
}

#define ZERO_ACC2(acc) \
    _Pragma("unroll") for (int _i = 0; _i < 2; ++_i) \
    _Pragma("unroll") for (int _j = 0; _j < 4; ++_j) \
    _Pragma("unroll") for (int _q = 0; _q < 4; ++_q) acc[_i][_j][_q] = 0.f;

// Tile: [128][36] floats = 18432 B. Row stride 144 B.
// Thread load map (512 thr): row = tid>>2 (0..127), two float4 at
// byte cols (tid&3)*16 and (tid&3)*16+64.

// ---------------------------------------------------------------------------
// Core (single-B): C(128x128) += A(128x768).B(128x768)^T. 512 threads,
// warp 4(M)x4(N), warp tile 32x32. 3-stage cp.async, stage = 36864 B.
// pa/pb: this thread's global row pointer (row tid>>2) at col (tid&3)*4.
// ---------------------------------------------------------------------------
__device__ __forceinline__ void gemm3s(
    unsigned smu, const float* pa, const float* pb,
    float acc[2][4][4], int tid)
{
    const int lane = tid & 31, warp = tid >> 5;
    const int wm = warp & 3, wn = warp >> 2;
    const int r = lane >> 2, cc = lane & 3;
    const unsigned dA = smu + (unsigned)((tid >> 2) * 144 + (tid & 3) * 16);

    unsigned aRow[2], bRow[4];
#pragma unroll
    for (int mi = 0; mi < 2; ++mi) aRow[mi] = (unsigned)((wm * 32 + mi * 16 + r) * 144);
#pragma unroll
    for (int ni = 0; ni < 4; ++ni) bRow[ni] = (unsigned)((wn * 32 + ni * 8 + r) * 144 + 18432);

    auto LOAD = [&](int kt) {
        unsigned off = (unsigned)(kt % 3) * 36864u;
        int ko = kt * 32;
        cpa16(dA + off,           pa + ko);
        cpa16(dA + off + 64,      pa + ko + 16);
        cpa16(dA + off + 18432u,      pb + ko);
        cpa16(dA + off + 18432u + 64, pb + ko + 16);
    };

    LOAD(0); cpa_commit();
    LOAD(1); cpa_commit();
    for (int kt = 0; kt < KTILES; ++kt) {
        cpa_wait1();
        __syncthreads();
        if (kt + 2 < KTILES) LOAD(kt + 2);
        cpa_commit();
        unsigned base = smu + (unsigned)(kt % 3) * 36864u;
#pragma unroll
        for (int k8 = 0; k8 < 4; ++k8) {
            unsigned ko = (unsigned)((k8 * 8 + cc) * 4);
            unsigned a[2][4];
#pragma unroll
            for (int mi = 0; mi < 2; ++mi) {
                unsigned p = base + aRow[mi] + ko;
                a[mi][0] = rna(lds32(p));
                a[mi][1] = rna(lds32(p + 8 * 144));
                a[mi][2] = rna(lds32(p + 16));
                a[mi][3] = rna(lds32(p + 8 * 144 + 16));
            }
#pragma unroll
            for (int ni = 0; ni < 4; ++ni) {
                unsigned p = base + bRow[ni] + ko;
                unsigned bb0 = rna(lds32(p)), bb1 = rna(lds32(p + 16));
#pragma unroll
                for (int mi = 0; mi < 2; ++mi)
                    mma8(acc[mi][ni], a[mi][0], a[mi][1], a[mi][2], a[mi][3], bb0, bb1);
            }
        }
    }
}

// ---------------------------------------------------------------------------
// Kernel 0: init start logits with o_b
// ---------------------------------------------------------------------------
__global__ void init_start_kernel(float* __restrict__ out, const float* __restrict__ ob)
{
    int i = blockIdx.x * 256 + threadIdx.x;
    if (i < START_SIZE) out[i] = ob[i % NTAG];
}

// ---------------------------------------------------------------------------
// Kernel 1: fused GLU start head, single K-pass (u and v together), 512 thr.
// Smem floats: [0,41472) pipeline 3 stages x 3 tiles; us 128x132 reuses [0,
// 16896); ow_s 41472, ub_s 42752, vb_s 42880. Total 43008 fl = 172032 B.
// ---------------------------------------------------------------------------
__global__ void __launch_bounds__(NT) glu_mma_kernel(
    const float* __restrict__ hid,
    const float* __restrict__ uw, const float* __restrict__ ub,
    const float* __restrict__ vw, const float* __restrict__ vb,
    const float* __restrict__ ow,
    float* __restrict__ out)
{
    extern __shared__ float sm[];
    const unsigned smu = s2u(sm);
    float* us   = sm;
    float* ow_s = sm + 41472;
    float* ub_s = sm + 42752;
    float* vb_s = sm + 42880;

    const int tid = threadIdx.x;
    const int nb = blockIdx.x * 128, mb = blockIdx.y * 128;

    for (int i = tid; i < NTAG * 128; i += NT)
        ow_s[i] = ow[(i >> 7) * H3 + nb + (i & 127)];
    if (tid < 128) { ub_s[tid] = ub[nb + tid]; vb_s[tid] = vb[nb + tid]; }

    const int grow = tid >> 2, gcol = (tid & 3) * 4;
    const float* pa = hid + (size_t)(mb + grow) * HD + gcol;
    const float* pu = uw + (size_t)(nb + grow) * HD + gcol;
    const float* pv = vw + (size_t)(nb + grow) * HD + gcol;

    const int lane = tid & 31, warp = tid >> 5;
    const int wm = warp & 3, wn = warp >> 2;
    const int r = lane >> 2, cc = lane & 3;
    const unsigned dA = smu + (unsigned)(grow * 144 + (tid & 3) * 16);

    unsigned aRow[2], bRow[4];
#pragma unroll
    for (int mi = 0; mi < 2; ++mi) aRow[mi] = (unsigned)((wm * 32 + mi * 16 + r) * 144);
#pragma unroll
    for (int ni = 0; ni < 4; ++ni) bRow[ni] = (unsigned)((wn * 32 + ni * 8 + r) * 144);

    auto LOAD = [&](int kt) {
        unsigned off = (unsigned)(kt % 3) * 55296u;   // 3 tiles per stage
        int ko = kt * 32;
        cpa16(dA + off,                pa + ko);
        cpa16(dA + off + 64,           pa + ko + 16);
        cpa16(dA + off + 18432u,       pu + ko);
        cpa16(dA + off + 18432u + 64,  pu + ko + 16);
        cpa16(dA + off + 36864u,       pv + ko);
        cpa16(dA + off + 36864u + 64,  pv + ko + 16);
    };

    float au[2][4][4], av[2][4][4];
    ZERO_ACC2(au);
    ZERO_ACC2(av);

    LOAD(0); cpa_commit();
    LOAD(1); cpa_commit();
    for (int kt = 0; kt < KTILES; ++kt) {
        cpa_wait1();
        __syncthreads();
        if (kt + 2 < KTILES) LOAD(kt + 2);
        cpa_commit();
        unsigned base = smu + (unsigned)(kt % 3) * 55296u;
#pragma unroll
        for (int k8 = 0; k8 < 4; ++k8) {
            unsigned ko = (unsigned)((k8 * 8 + cc) * 4);
            unsigned a[2][4];
#pragma unroll
            for (int mi = 0; mi < 2; ++mi) {
                unsigned p = base + aRow[mi] + ko;
                a[mi][0] = rna(lds32(p));
                a[mi][1] = rna(lds32(p + 8 * 144));
                a[mi][2] = rna(lds32(p + 16));
                a[mi][3] = rna(lds32(p + 8 * 144 + 16));
            }
#pragma unroll
            for (int ni = 0; ni < 4; ++ni) {
                unsigned pb_u = base + 18432u + bRow[ni] + ko;
                unsigned pb_v = base + 36864u + bRow[ni] + ko;
                unsigned u0 = rna(lds32(pb_u)), u1 = rna(lds32(pb_u + 16));
                unsigned v0 = rna(lds32(pb_v)), v1 = rna(lds32(pb_v + 16));
#pragma unroll
                for (int mi = 0; mi < 2; ++mi) {
                    mma8(au[mi][ni], a[mi][0], a[mi][1], a[mi][2], a[mi][3], u0, u1);
                    mma8(av[mi][ni], a[mi][0], a[mi][1], a[mi][2], a[mi][3], v0, v1);
                }
            }
        }
    }

    // gate in registers -> us (pipeline smem region reused; safe: last sync'd
    // stage reads are done; us [0,16896) vs final-stage reads >= 27648)
#pragma unroll
    for (int mi = 0; mi < 2; ++mi) {
        int row = wm * 32 + mi * 16 + r;
#pragma unroll
        for (int ni = 0; ni < 4; ++ni) {
            int col = wn * 32 + ni * 8 + 2 * cc;
            float s0 = 1.f / (1.f + __expf(-(au[mi][ni][0] + ub_s[col])));
            float s1 = 1.f / (1.f + __expf(-(au[mi][ni][1] + ub_s[col + 1])));
            float s2 = 1.f / (1.f + __expf(-(au[mi][ni][2] + ub_s[col])));
            float s3 = 1.f / (1.f + __expf(-(au[mi][ni][3] + ub_s[col + 1])));
            us[row * 132 + col]           = s0 * (av[mi][ni][0] + vb_s[col]);
            us[row * 132 + col + 1]       = s1 * (av[mi][ni][1] + vb_s[col + 1]);
            us[(row + 8) * 132 + col]     = s2 * (av[mi][ni][2] + vb_s[col]);
            us[(row + 8) * 132 + col + 1] = s3 * (av[mi][ni][3] + vb_s[col + 1]);
        }
    }
    __syncthreads();

    // tag reduction + atomicAdd: 4 quarters of 32 cols each
    {
        const int row = tid & 127, quarter = tid >> 7;
        float t10[NTAG];
#pragma unroll
        for (int t = 0; t < NTAG; ++t) t10[t] = 0.f;
        const float* gr = us + row * 132 + quarter * 32;
        const float* owr = ow_s + quarter * 32;
#pragma unroll 4
        for (int n = 0; n < 32; ++n) {
            float g = gr[n];
#pragma unroll
            for (int t = 0; t < NTAG; ++t)
                t10[t] = fmaf(g, owr[t * 128 + n], t10[t]);
        }
        float* so = out + (size_t)(mb + row) * NTAG;
#pragma unroll
        for (int t = 0; t < NTAG; ++t) atomicAdd(so + t, t10[t]);
    }
}

// ---------------------------------------------------------------------------
// Kernel 2: k projection  g_k = hid @ kw^T + kb
// ---------------------------------------------------------------------------
__global__ void __launch_bounds__(NT) kproj_mma_kernel(
    const float* __restrict__ hid, const float* __restrict__ kw,
    const float* __restrict__ kb)
{
    extern __shared__ float sm[];
    const unsigned smu = s2u(sm);
    float* kb_s = sm + 27648;
    const int tid = threadIdx.x;
    const int nb = blockIdx.x * 128, mb = blockIdx.y * 128;
    if (tid < 128) kb_s[tid] = kb[nb + tid];

    const int grow = tid >> 2, gcol = (tid & 3) * 4;
    const float* pa = hid + (size_t)(mb + grow) * HD + gcol;
    const float* pb = kw + (size_t)(nb + grow) * HD + gcol;

    float acc[2][4][4];
    ZERO_ACC2(acc);
    gemm3s(smu, pa, pb, acc, tid);

    const int lane = tid & 31, warp = tid >> 5;
    const int wm = warp & 3, wn = warp >> 2;
    const int r = lane >> 2, cc = lane & 3;
#pragma unroll
    for (int mi = 0; mi < 2; ++mi) {
        int row = wm * 32 + mi * 16 + r;
#pragma unroll
        for (int ni = 0; ni < 4; ++ni) {
            int col = wn * 32 + ni * 8 + 2 * cc;
            float2 w0 = { acc[mi][ni][0] + kb_s[col], acc[mi][ni][1] + kb_s[col + 1] };
            float2 w1 = { acc[mi][ni][2] + kb_s[col], acc[mi][ni][3] + kb_s[col + 1] };
            *(float2*)(g_k + (size_t)(mb + row) * HD + nb + col) = w0;
            *(float2*)(g_k + (size_t)(mb + row + 8) * HD + nb + col) = w1;
        }
    }
}

// ---------------------------------------------------------------------------
// Kernel 3: gathered q projection (entity_start int32)
// ---------------------------------------------------------------------------
__global__ void __launch_bounds__(NT) qproj_mma_kernel(
    const float* __restrict__ hid, const float* __restrict__ qw,
    const float* __restrict__ qb, const int* __restrict__ ent)
{
    extern __shared__ float sm[];
    const unsigned smu = s2u(sm);
    float* qb_s = sm + 27648;
    int* idxs = (int*)(sm + 27776);
    const int tid = threadIdx.x;
    const int nb = blockIdx.x * 128, b = blockIdx.y;
    if (tid < 128) { qb_s[tid] = qb[nb + tid]; idxs[tid] = ent[b * EZ + tid]; }
    __syncthreads();

    const int grow = tid >> 2, gcol = (tid & 3) * 4;
    const float* pa = hid + ((size_t)b * SQ + idxs[grow]) * HD + gcol;
    const float* pb = qw + (size_t)(nb + grow) * HD + gcol;

    float acc[2][4][4];
    ZERO_ACC2(acc);
    gemm3s(smu, pa, pb, acc, tid);

    const int lane = tid & 31, warp = tid >> 5;
    const int wm = warp & 3, wn = warp >> 2;
    const int r = lane >> 2, cc = lane & 3;
#pragma unroll
    for (int mi = 0; mi < 2; ++mi) {
        int row = wm * 32 + mi * 16 + r;
#pragma unroll
        for (int ni = 0; ni < 4; ++ni) {
            int col = wn * 32 + ni * 8 + 2 * cc;
            float2 w0 = { acc[mi][ni][0] + qb_s[col], acc[mi][ni][1] + qb_s[col + 1] };
            float2 w1 = { acc[mi][ni][2] + qb_s[col], acc[mi][ni][3] + qb_s[col + 1] };
            *(float2*)(g_q + ((size_t)b * EZ + row) * HD + nb + col) = w0;
            *(float2*)(g_q + ((size_t)b * EZ + row + 8) * HD + nb + col) = w1;
        }
    }
}

// ---------------------------------------------------------------------------
// Kernel 4: end logits = (q . k)/96, masked (mask int32)
// ---------------------------------------------------------------------------
__global__ void __launch_bounds__(NT) end_mma_kernel(
    const int* __restrict__ mask, float* __restrict__ out)
{
    extern __shared__ float sm[];
    const unsigned smu = s2u(sm);
    int* mask_s = (int*)(sm + 27648);
    const int tid = threadIdx.x;
    const int nb = blockIdx.x * 128, b = blockIdx.y;   // nb over S
    if (tid < 128) mask_s[tid] = mask[b * SQ + nb + tid];
    __syncthreads();

    const int grow = tid >> 2, gcol = (tid & 3) * 4;
    const float* pa = g_q + ((size_t)b * EZ + grow) * HD + gcol;
    const float* pb = g_k + ((size_t)b * SQ + nb + grow) * HD + gcol;

    float acc[2][4][4];
    ZERO_ACC2(acc);
    gemm3s(smu, pa, pb, acc, tid);

    const int lane = tid & 31, warp = tid >> 5;
    const int wm = warp & 3, wn = warp >> 2;
    const int r = lane >> 2, cc = lane & 3;
    float* ob = out + START_SIZE + (size_t)b * EZ * SQ;
#pragma unroll
    for (int mi = 0; mi < 2; ++mi) {
        int row = wm * 32 + mi * 16 + r;
#pragma unroll
        for (int ni = 0; ni < 4; ++ni) {
            int col = wn * 32 + ni * 8 + 2 * cc;
            int m0 = mask_s[col], m1 = mask_s[col + 1];
            float2 w0 = { m0 ? acc[mi][ni][0] * INV96 : -50000.f,
                          m1 ? acc[mi][ni][1] * INV96 : -50000.f };
            float2 w1 = { m0 ? acc[mi][ni][2] * INV96 : -50000.f,
                          m1 ? acc[mi][ni][3] * INV96 : -50000.f };
            *(float2*)(ob + (size_t)row * SQ + nb + col) = w0;
            *(float2*)(ob + (size_t)(row + 8) * SQ + nb + col) = w1;
        }
    }
}

// ---------------------------------------------------------------------------
// Launch
// ---------------------------------------------------------------------------
extern "C" void kernel_launch(void* const* d_in, const int* in_sizes, int n_in,
                              void* d_out, int out_size)
{
    const float* hid  = (const float*)d_in[0];
    const float* uw   = (const float*)d_in[1];
    const float* ub   = (const float*)d_in[2];
    const float* vw   = (const float*)d_in[3];
    const float* vb   = (const float*)d_in[4];
    const float* ow   = (const float*)d_in[5];
    const float* ob   = (const float*)d_in[6];
    const float* qw   = (const float*)d_in[7];
    const float* qb   = (const float*)d_in[8];
    const float* kw   = (const float*)d_in[9];
    const float* kb   = (const float*)d_in[10];
    const int*   ent  = (const int*)d_in[11];
    const int*   mask = (const int*)d_in[12];
    float* out = (float*)d_out;

    const int GLU_SMEM = 43008 * 4;   // 172032
    const int STD_SMEM = 27904 * 4;   // 111616
    static int attr_done = 0;
    if (!attr_done) {
        cudaFuncSetAttribute(glu_mma_kernel, cudaFuncAttributeMaxDynamicSharedMemorySize, GLU_SMEM);
        cudaFuncSetAttribute(kproj_mma_kernel, cudaFuncAttributeMaxDynamicSharedMemorySize, STD_SMEM);
        cudaFuncSetAttribute(qproj_mma_kernel, cudaFuncAttributeMaxDynamicSharedMemorySize, STD_SMEM);
        cudaFuncSetAttribute(end_mma_kernel, cudaFuncAttributeMaxDynamicSharedMemorySize, STD_SMEM);
        attr_done = 1;
    }

    init_start_kernel<<<(START_SIZE + 255) / 256, 256>>>(out, ob);
    glu_mma_kernel<<<dim3(H3 / 128, M_ALL / 128), NT, GLU_SMEM>>>(hid, uw, ub, vw, vb, ow, out);
    kproj_mma_kernel<<<dim3(HD / 128, M_ALL / 128), NT, STD_SMEM>>>(hid, kw, kb);
    qproj_mma_kernel<<<dim3(HD / 128, BZ), NT, STD_SMEM>>>(hid, qw, qb, ent);
    end_mma_kernel<<<dim3(SQ / 128, BZ), NT, STD_SMEM>>>(mask, out);
}

// round 7
// speedup vs baseline: 1.2259x; 1.2259x over previous
#include <cuda_runtime.h>

// ---------------------------------------------------------------------------
// Problem constants
// ---------------------------------------------------------------------------
#define BZ   16
#define SQ   2048
#define HD   768
#define EZ   128
#define NTAG 10
#define H3   2304
#define M_ALL (BZ * SQ)            // 32768
#define START_SIZE (M_ALL * NTAG)  // 327680
#define INV96 (1.0f / 96.0f)
#define KTILES 24                  // 768 / 32

// Scratch
__device__ float g_k[M_ALL * HD];
__device__ float g_q[BZ * EZ * HD];

// ---------------------------------------------------------------------------
// PTX helpers (baseline compute_100: cp.async + mma.sync tf32 + ldmatrix)
// ---------------------------------------------------------------------------
__device__ __forceinline__ unsigned s2u(const void* p) {
    unsigned a;
    asm("{ .reg .u64 t; cvta.to.shared.u64 t, %1; cvt.u32.u64 %0, t; }"
        : "=r"(a) : "l"(p));
    return a;
}
__device__ __forceinline__ unsigned rna(float x) {
    unsigned r;
    asm("cvt.rna.tf32.f32 %0, %1;" : "=r"(r) : "f"(x));
    return r;
}
__device__ __forceinline__ unsigned rnau(unsigned x) {
    unsigned r;
    asm("cvt.rna.tf32.f32 %0, %1;" : "=r"(r) : "f"(__uint_as_float(x)));
    return r;
}
__device__ __forceinline__ void ldm4(unsigned addr, unsigned q[4]) {
    asm volatile(
        "ldmatrix.sync.aligned.m8n8.x4.shared.b16 {%0,%1,%2,%3}, [%4];"
        : "=r"(q[0]), "=r"(q[1]), "=r"(q[2]), "=r"(q[3]) : "r"(addr));
}
__device__ __forceinline__ void cpa16(unsigned d, const float* s) {
    asm volatile("cp.async.cg.shared.global [%0], [%1], 16;" :: "r"(d), "l"(s));
}
__device__ __forceinline__ void cpa_commit() {
    asm volatile("cp.async.commit_group;" ::: "memory");
}
__device__ __forceinline__ void cpa_wait1() {
    asm volatile("cp.async.wait_group 1;" ::: "memory");
}
__device__ __forceinline__ void mma8(float d[4], unsigned a0, unsigned a1,
                                     unsigned a2, unsigned a3,
                                     unsigned b0, unsigned b1) {
    asm volatile(
        "mma.sync.aligned.m16n8k8.row.col.f32.tf32.tf32.f32 "
        "{%0,%1,%2,%3}, {%4,%5,%6,%7}, {%8,%9}, {%0,%1,%2,%3};"
        : "+f"(d[0]), "+f"(d[1]), "+f"(d[2]), "+f"(d[3])
        : "r"(a0), "r"(a1), "r"(a2), "r"(a3), "r"(b0), "r"(b1));
}

#define ZERO_ACC(acc) \
    _Pragma("unroll") for (int _i = 0; _i < 4; ++_i) \
    _Pragma("unroll") for (int _j = 0; _j < 4; ++_j) \
    _Pragma("unroll") for (int _q = 0; _q < 4; ++_q) acc[_i][_j][_q] = 0.f;

// Tile: [128][36] floats = 18432 B, row stride 144 B (odd multiple of 16B ->
// 8 consecutive rows hit 8 distinct 16B bank groups: ldmatrix conflict-free).
//
// ldmatrix fragment offsets (lane-dependent, byte units, relative to tile):
//  A (warp M-block wm, sub-tile mi of 16 rows):
//   matrix m = lane>>3: row = base + (lane&7) + ((lane>>3)&1)*8, colhalf = lane>>4
//  B (two ni per x4): matrix m: ni_local = m>>1, colhalf = m&1

// ---------------------------------------------------------------------------
// Core (single-B): C(128x128) += A(128x768).B(128x768)^T. 256 threads, warp
// grid 2(M)x4(N), warp tile 64x32. 3-stage cp.async, stage = 36864 B.
// ---------------------------------------------------------------------------
__device__ __forceinline__ void gemm3s(
    unsigned smu,
    const float* a0, const float* a1, const float* a2, const float* a3,
    const float* b0,
    float acc[4][4][4], int tid)
{
    const int lane = tid & 31, warp = tid >> 5;
    const int wm = warp & 1, wn = warp >> 1;
    const unsigned dA = smu + (unsigned)(((tid >> 3) * 36 + (tid & 7) * 4) * 4);
    const float* asrc[4] = {a0, a1, a2, a3};

    unsigned offA[4], offB[2];
#pragma unroll
    for (int mi = 0; mi < 4; ++mi)
        offA[mi] = (unsigned)((wm * 64 + mi * 16 + (lane & 7) + ((lane >> 3) & 1) * 8) * 144
                              + (lane >> 4) * 16);
#pragma unroll
    for (int g = 0; g < 2; ++g)
        offB[g] = (unsigned)((wn * 32 + (g * 2 + (lane >> 4)) * 8 + (lane & 7)) * 144
                             + ((lane >> 3) & 1) * 16 + 18432);

    auto LOAD = [&](int kt) {
        unsigned off = (unsigned)(kt % 3) * 36864u;
        int ko = kt * 32;
#pragma unroll
        for (int j = 0; j < 4; ++j) {
            cpa16(dA + off + j * 4608u, asrc[j] + ko);
            cpa16(dA + off + 18432u + j * 4608u, b0 + (size_t)j * 32 * HD + ko);
        }
    };

    LOAD(0); cpa_commit();
    LOAD(1); cpa_commit();
    for (int kt = 0; kt < KTILES; ++kt) {
        cpa_wait1();
        __syncthreads();
        if (kt + 2 < KTILES) LOAD(kt + 2);
        cpa_commit();
        unsigned base = smu + (unsigned)(kt % 3) * 36864u;
#pragma unroll
        for (int k8 = 0; k8 < 4; ++k8) {
            unsigned kb = (unsigned)(k8 * 32);
            unsigned a[4][4], bf[2][4];
#pragma unroll
            for (int mi = 0; mi < 4; ++mi) {
                ldm4(base + offA[mi] + kb, a[mi]);
#pragma unroll
                for (int q = 0; q < 4; ++q) a[mi][q] = rnau(a[mi][q]);
            }
#pragma unroll
            for (int g = 0; g < 2; ++g) {
                ldm4(base + offB[g] + kb, bf[g]);
#pragma unroll
                for (int q = 0; q < 4; ++q) bf[g][q] = rnau(bf[g][q]);
            }
#pragma unroll
            for (int ni = 0; ni < 4; ++ni) {
                unsigned bb0 = bf[ni >> 1][(ni & 1) * 2];
                unsigned bb1 = bf[ni >> 1][(ni & 1) * 2 + 1];
#pragma unroll
                for (int mi = 0; mi < 4; ++mi)
                    mma8(acc[mi][ni], a[mi][0], a[mi][1], a[mi][2], a[mi][3], bb0, bb1);
            }
        }
    }
}

// ---------------------------------------------------------------------------
// Kernel 0: init start logits with o_b (GLU accumulates on top)
// ---------------------------------------------------------------------------
__global__ void init_start_kernel(float* __restrict__ out, const float* __restrict__ ob)
{
    int i = blockIdx.x * 256 + threadIdx.x;
    if (i < START_SIZE) out[i] = ob[i % NTAG];
}

// ---------------------------------------------------------------------------
// Kernel 1: fused GLU start head, single K-pass (u and v share A fragments),
// ldmatrix fragment loads, gate in registers, tag-reduce epilogue.
// Smem floats: [0,41472) pipeline 3 stages x 3 tiles (A,Bu,Bv);
// us 128x132 reuses [0,16896); ow_s 41472, ub_s 42752, vb_s 42880.
// Total 43008 fl = 172032 B.
// ---------------------------------------------------------------------------
__global__ void __launch_bounds__(256) glu_mma_kernel(
    const float* __restrict__ hid,
    const float* __restrict__ uw, const float* __restrict__ ub,
    const float* __restrict__ vw, const float* __restrict__ vb,
    const float* __restrict__ ow,
    float* __restrict__ out)
{
    extern __shared__ float sm[];
    const unsigned smu = s2u(sm);
    float* us   = sm;
    float* ow_s = sm + 41472;
    float* ub_s = sm + 42752;
    float* vb_s = sm + 42880;

    const int tid = threadIdx.x;
    const int nb = blockIdx.x * 128, mb = blockIdx.y * 128;

    for (int i = tid; i < NTAG * 128; i += 256)
        ow_s[i] = ow[(i >> 7) * H3 + nb + (i & 127)];
    if (tid < 128) { ub_s[tid] = ub[nb + tid]; vb_s[tid] = vb[nb + tid]; }

    const int arow = tid >> 3, kch = tid & 7;
    const float* ha[4];
#pragma unroll
    for (int j = 0; j < 4; ++j)
        ha[j] = hid + (size_t)(mb + arow + 32 * j) * HD + kch * 4;
    const float* bu = uw + (size_t)(nb + arow) * HD + kch * 4;
    const float* bv = vw + (size_t)(nb + arow) * HD + kch * 4;

    const int lane = tid & 31, warp = tid >> 5;
    const int wm = warp & 1, wn = warp >> 1;
    const int r = lane >> 2, cc = lane & 3;
    const unsigned dA = smu + (unsigned)((arow * 36 + kch * 4) * 4);

    unsigned offA[4], offB[2];
#pragma unroll
    for (int mi = 0; mi < 4; ++mi)
        offA[mi] = (unsigned)((wm * 64 + mi * 16 + (lane & 7) + ((lane >> 3) & 1) * 8) * 144
                              + (lane >> 4) * 16);
#pragma unroll
    for (int g = 0; g < 2; ++g)
        offB[g] = (unsigned)((wn * 32 + (g * 2 + (lane >> 4)) * 8 + (lane & 7)) * 144
                             + ((lane >> 3) & 1) * 16 + 18432);

    auto LOAD = [&](int kt) {
        unsigned off = (unsigned)(kt % 3) * 55296u;   // 3 tiles per stage
        int ko = kt * 32;
#pragma unroll
        for (int j = 0; j < 4; ++j) {
            cpa16(dA + off + j * 4608u,           ha[j] + ko);
            cpa16(dA + off + 18432u + j * 4608u,  bu + (size_t)j * 32 * HD + ko);
            cpa16(dA + off + 36864u + j * 4608u,  bv + (size_t)j * 32 * HD + ko);
        }
    };

    float au[4][4][4], av[4][4][4];
    ZERO_ACC(au);
    ZERO_ACC(av);

    LOAD(0); cpa_commit();
    LOAD(1); cpa_commit();
    for (int kt = 0; kt < KTILES; ++kt) {
        cpa_wait1();
        __syncthreads();
        if (kt + 2 < KTILES) LOAD(kt + 2);
        cpa_commit();
        unsigned base = smu + (unsigned)(kt % 3) * 55296u;
#pragma unroll
        for (int k8 = 0; k8 < 4; ++k8) {
            unsigned kb = (unsigned)(k8 * 32);
            unsigned a[4][4], bfu[2][4], bfv[2][4];
#pragma unroll
            for (int mi = 0; mi < 4; ++mi) {
                ldm4(base + offA[mi] + kb, a[mi]);
#pragma unroll
                for (int q = 0; q < 4; ++q) a[mi][q] = rnau(a[mi][q]);
            }
#pragma unroll
            for (int g = 0; g < 2; ++g) {
                ldm4(base + offB[g] + kb, bfu[g]);
                ldm4(base + offB[g] + 18432u + kb, bfv[g]);
#pragma unroll
                for (int q = 0; q < 4; ++q) {
                    bfu[g][q] = rnau(bfu[g][q]);
                    bfv[g][q] = rnau(bfv[g][q]);
                }
            }
#pragma unroll
            for (int ni = 0; ni < 4; ++ni) {
                unsigned u0 = bfu[ni >> 1][(ni & 1) * 2];
                unsigned u1 = bfu[ni >> 1][(ni & 1) * 2 + 1];
                unsigned v0 = bfv[ni >> 1][(ni & 1) * 2];
                unsigned v1 = bfv[ni >> 1][(ni & 1) * 2 + 1];
#pragma unroll
                for (int mi = 0; mi < 4; ++mi) {
                    mma8(au[mi][ni], a[mi][0], a[mi][1], a[mi][2], a[mi][3], u0, u1);
                    mma8(av[mi][ni], a[mi][0], a[mi][1], a[mi][2], a[mi][3], v0, v1);
                }
            }
        }
    }

    // gate in registers -> us (pipeline smem region reused after final sync;
    // us [0,16896) vs final-stage reads >= 27648)
#pragma unroll
    for (int mi = 0; mi < 4; ++mi) {
        int row = wm * 64 + mi * 16 + r;
#pragma unroll
        for (int ni = 0; ni < 4; ++ni) {
            int col = wn * 32 + ni * 8 + 2 * cc;
            float s0 = 1.f / (1.f + __expf(-(au[mi][ni][0] + ub_s[col])));
            float s1 = 1.f / (1.f + __expf(-(au[mi][ni][1] + ub_s[col + 1])));
            float s2 = 1.f / (1.f + __expf(-(au[mi][ni][2] + ub_s[col])));
            float s3 = 1.f / (1.f + __expf(-(au[mi][ni][3] + ub_s[col + 1])));
            us[row * 132 + col]           = s0 * (av[mi][ni][0] + vb_s[col]);
            us[row * 132 + col + 1]       = s1 * (av[mi][ni][1] + vb_s[col + 1]);
            us[(row + 8) * 132 + col]     = s2 * (av[mi][ni][2] + vb_s[col]);
            us[(row + 8) * 132 + col + 1] = s3 * (av[mi][ni][3] + vb_s[col + 1]);
        }
    }
    __syncthreads();

    // tag reduction + atomicAdd
    {
        const int row = tid & 127, half = tid >> 7;
        float t10[NTAG];
#pragma unroll
        for (int t = 0; t < NTAG; ++t) t10[t] = 0.f;
        const float* gr = us + row * 132 + half * 64;
        const float* owr = ow_s + half * 64;
#pragma unroll 4
        for (int n = 0; n < 64; ++n) {
            float g = gr[n];
#pragma unroll
            for (int t = 0; t < NTAG; ++t)
                t10[t] = fmaf(g, owr[t * 128 + n], t10[t]);
        }
        float* so = out + (size_t)(mb + row) * NTAG;
#pragma unroll
        for (int t = 0; t < NTAG; ++t) atomicAdd(so + t, t10[t]);
    }
}

// ---------------------------------------------------------------------------
// Kernel 2: k projection  g_k = hid @ kw^T + kb
// ---------------------------------------------------------------------------
__global__ void __launch_bounds__(256) kproj_mma_kernel(
    const float* __restrict__ hid, const float* __restrict__ kw,
    const float* __restrict__ kb)
{
    extern __shared__ float sm[];
    const unsigned smu = s2u(sm);
    float* kb_s = sm + 27648;
    const int tid = threadIdx.x;
    const int nb = blockIdx.x * 128, mb = blockIdx.y * 128;
    if (tid < 128) kb_s[tid] = kb[nb + tid];

    const int arow = tid >> 3, kch = tid & 7;
    const float* ha[4];
#pragma unroll
    for (int j = 0; j < 4; ++j)
        ha[j] = hid + (size_t)(mb + arow + 32 * j) * HD + kch * 4;
    const float* bk = kw + (size_t)(nb + arow) * HD + kch * 4;

    float acc[4][4][4];
    ZERO_ACC(acc);
    gemm3s(smu, ha[0], ha[1], ha[2], ha[3], bk, acc, tid);

    const int lane = tid & 31, warp = tid >> 5;
    const int wm = warp & 1, wn = warp >> 1;
    const int r = lane >> 2, cc = lane & 3;
#pragma unroll
    for (int mi = 0; mi < 4; ++mi) {
        int row = wm * 64 + mi * 16 + r;
#pragma unroll
        for (int ni = 0; ni < 4; ++ni) {
            int col = wn * 32 + ni * 8 + 2 * cc;
            float2 w0 = { acc[mi][ni][0] + kb_s[col], acc[mi][ni][1] + kb_s[col + 1] };
            float2 w1 = { acc[mi][ni][2] + kb_s[col], acc[mi][ni][3] + kb_s[col + 1] };
            *(float2*)(g_k + (size_t)(mb + row) * HD + nb + col) = w0;
            *(float2*)(g_k + (size_t)(mb + row + 8) * HD + nb + col) = w1;
        }
    }
}

// ---------------------------------------------------------------------------
// Kernel 3: gathered q projection (entity_start int32)
// ---------------------------------------------------------------------------
__global__ void __launch_bounds__(256) qproj_mma_kernel(
    const float* __restrict__ hid, const float* __restrict__ qw,
    const float* __restrict__ qb, const int* __restrict__ ent)
{
    extern __shared__ float sm[];
    const unsigned smu = s2u(sm);
    float* qb_s = sm + 27648;
    int* idxs = (int*)(sm + 27776);
    const int tid = threadIdx.x;
    const int nb = blockIdx.x * 128, b = blockIdx.y;
    if (tid < 128) { qb_s[tid] = qb[nb + tid]; idxs[tid] = ent[b * EZ + tid]; }
    __syncthreads();

    const int arow = tid >> 3, kch = tid & 7;
    const float* ha[4];
#pragma unroll
    for (int j = 0; j < 4; ++j)
        ha[j] = hid + ((size_t)b * SQ + idxs[arow + 32 * j]) * HD + kch * 4;
    const float* bq = qw + (size_t)(nb + arow) * HD + kch * 4;

    float acc[4][4][4];
    ZERO_ACC(acc);
    gemm3s(smu, ha[0], ha[1], ha[2], ha[3], bq, acc, tid);

    const int lane = tid & 31, warp = tid >> 5;
    const int wm = warp & 1, wn = warp >> 1;
    const int r = lane >> 2, cc = lane & 3;
#pragma unroll
    for (int mi = 0; mi < 4; ++mi) {
        int row = wm * 64 + mi * 16 + r;
#pragma unroll
        for (int ni = 0; ni < 4; ++ni) {
            int col = wn * 32 + ni * 8 + 2 * cc;
            float2 w0 = { acc[mi][ni][0] + qb_s[col], acc[mi][ni][1] + qb_s[col + 1] };
            float2 w1 = { acc[mi][ni][2] + qb_s[col], acc[mi][ni][3] + qb_s[col + 1] };
            *(float2*)(g_q + ((size_t)b * EZ + row) * HD + nb + col) = w0;
            *(float2*)(g_q + ((size_t)b * EZ + row + 8) * HD + nb + col) = w1;
        }
    }
}

// ---------------------------------------------------------------------------
// Kernel 4: end logits = (q . k)/96, masked (mask int32)
// ---------------------------------------------------------------------------
__global__ void __launch_bounds__(256) end_mma_kernel(
    const int* __restrict__ mask, float* __restrict__ out)
{
    extern __shared__ float sm[];
    const unsigned smu = s2u(sm);
    int* mask_s = (int*)(sm + 27648);
    const int tid = threadIdx.x;
    const int nb = blockIdx.x * 128, b = blockIdx.y;   // nb over S
    if (tid < 128) mask_s[tid] = mask[b * SQ + nb + tid];
    __syncthreads();

    const int arow = tid >> 3, kch = tid & 7;
    const float* ha[4];
#pragma unroll
    for (int j = 0; j < 4; ++j)
        ha[j] = g_q + ((size_t)b * EZ + arow + 32 * j) * HD + kch * 4;
    const float* bk = g_k + ((size_t)b * SQ + nb + arow) * HD + kch * 4;

    float acc[4][4][4];
    ZERO_ACC(acc);
    gemm3s(smu, ha[0], ha[1], ha[2], ha[3], bk, acc, tid);

    const int lane = tid & 31, warp = tid >> 5;
    const int wm = warp & 1, wn = warp >> 1;
    const int r = lane >> 2, cc = lane & 3;
    float* ob = out + START_SIZE + (size_t)b * EZ * SQ;
#pragma unroll
    for (int mi = 0; mi < 4; ++mi) {
        int row = wm * 64 + mi * 16 + r;
#pragma unroll
        for (int ni = 0; ni < 4; ++ni) {
            int col = wn * 32 + ni * 8 + 2 * cc;
            int m0 = mask_s[col], m1 = mask_s[col + 1];
            float2 w0 = { m0 ? acc[mi][ni][0] * INV96 : -50000.f,
                          m1 ? acc[mi][ni][1] * INV96 : -50000.f };
            float2 w1 = { m0 ? acc[mi][ni][2] * INV96 : -50000.f,
                          m1 ? acc[mi][ni][3] * INV96 : -50000.f };
            *(float2*)(ob + (size_t)row * SQ + nb + col) = w0;
            *(float2*)(ob + (size_t)(row + 8) * SQ + nb + col) = w1;
        }
    }
}

// ---------------------------------------------------------------------------
// Launch
// ---------------------------------------------------------------------------
extern "C" void kernel_launch(void* const* d_in, const int* in_sizes, int n_in,
                              void* d_out, int out_size)
{
    const float* hid  = (const float*)d_in[0];
    const float* uw   = (const float*)d_in[1];
    const float* ub   = (const float*)d_in[2];
    const float* vw   = (const float*)d_in[3];
    const float* vb   = (const float*)d_in[4];
    const float* ow   = (const float*)d_in[5];
    const float* ob   = (const float*)d_in[6];
    const float* qw   = (const float*)d_in[7];
    const float* qb   = (const float*)d_in[8];
    const float* kw   = (const float*)d_in[9];
    const float* kb   = (const float*)d_in[10];
    const int*   ent  = (const int*)d_in[11];
    const int*   mask = (const int*)d_in[12];
    float* out = (float*)d_out;

    const int GLU_SMEM = 43008 * 4;   // 172032
    const int STD_SMEM = 27904 * 4;   // 111616
    static int attr_done = 0;
    if (!attr_done) {
        cudaFuncSetAttribute(glu_mma_kernel, cudaFuncAttributeMaxDynamicSharedMemorySize, GLU_SMEM);
        cudaFuncSetAttribute(kproj_mma_kernel, cudaFuncAttributeMaxDynamicSharedMemorySize, STD_SMEM);
        cudaFuncSetAttribute(qproj_mma_kernel, cudaFuncAttributeMaxDynamicSharedMemorySize, STD_SMEM);
        cudaFuncSetAttribute(end_mma_kernel, cudaFuncAttributeMaxDynamicSharedMemorySize, STD_SMEM);
        attr_done = 1;
    }

    init_start_kernel<<<(START_SIZE + 255) / 256, 256>>>(out, ob);
    glu_mma_kernel<<<dim3(H3 / 128, M_ALL / 128), 256, GLU_SMEM>>>(hid, uw, ub, vw, vb, ow, out);
    kproj_mma_kernel<<<dim3(HD / 128, M_ALL / 128), 256, STD_SMEM>>>(hid, kw, kb);
    qproj_mma_kernel<<<dim3(HD / 128, BZ), 256, STD_SMEM>>>(hid, qw, qb, ent);
    end_mma_kernel<<<dim3(SQ / 128, BZ), 256, STD_SMEM>>>(mask, out);
}